// round 4
// baseline (speedup 1.0000x reference)
#include <cuda_runtime.h>
#include <cstdint>

// ---------------------------------------------------------------------------
// T2FN: fusion = sum_t (a1 ⊗ v1 ⊗ x1)  [B, 49*49*97], then 3-layer MLP.
// Stage 1: materialize fusion (fp32) into a __device__ scratch buffer.
// Stage 2: split-K GEMM fusion[128,232897] @ W1[232897,128] -> 296 partials.
// Stage 3: reduce partials + bias/relu + h1@W2 relu + h2@W3 sigmoid*6-3.
// All fp32; inner loops use packed fma.rn.f32x2 (Blackwell FFMA2).
// ---------------------------------------------------------------------------

typedef unsigned long long u64;

constexpr int B_  = 128;
constexpr int T_  = 64;
constexpr int A_  = 48;
constexpr int V_  = 48;
constexpr int X_  = 96;
constexpr int AI  = A_ + 1;      // 49
constexpr int VJ  = V_ + 1;      // 49
constexpr int XK  = X_ + 1;      // 97
constexpr int IJ  = AI * VJ;     // 2401
constexpr int FD  = IJ * XK;     // 232897
constexpr int PF  = 128;
constexpr int NSPLIT = 296;      // split-K CTAs for the big GEMM
constexpr int KT  = 16;          // GEMM K-tile
constexpr int NTILES = (FD + KT - 1) / KT;   // 14557

// scratch (static device allocations are allowed)
__device__ float g_fusion[(size_t)B_ * FD];          // ~119 MB
__device__ float g_part[(size_t)NSPLIT * B_ * PF];   // ~19.4 MB

__device__ __forceinline__ u64 pack2(float lo, float hi) {
    u64 r;
    asm("mov.b64 %0, {%1, %2};" : "=l"(r) : "f"(lo), "f"(hi));
    return r;
}
__device__ __forceinline__ void fma2(u64& acc, u64 a, u64 b) {
    asm("fma.rn.f32x2 %0, %1, %2, %0;" : "+l"(acc) : "l"(a), "l"(b));
}
__device__ __forceinline__ void unpack2(u64 v, float& lo, float& hi) {
    lo = __uint_as_float((unsigned)(v & 0xffffffffull));
    hi = __uint_as_float((unsigned)(v >> 32));
}

// ---------------------------------------------------------------------------
// Stage 1: fusion formation.
// grid = (ij_tiles=10, k_tiles=2, b=128), 256 threads.
// CTA computes a [256 ij x 64 k] tile of fusion[b] = sum_t av[ij,t]*x1[t,k].
// av staged in smem (each thread builds one ij column), x1 staged in smem,
// then register-blocked 8x8 micro-tile GEMM over t with FFMA2.
// ---------------------------------------------------------------------------
__global__ void __launch_bounds__(256)
fusion_kernel(const float* __restrict__ audio,
              const float* __restrict__ video,
              const float* __restrict__ text)
{
    __shared__ __align__(16) float av_s[32][256];   // [t-chunk][ij]  32 KB
    __shared__ __align__(16) float xs[32][64];      // [t-chunk][k]    8 KB

    const int b      = blockIdx.z;
    const int ijbase = blockIdx.x * 256;
    const int kbase  = blockIdx.y * 64;
    const int tid    = threadIdx.x;
    const int tr     = tid >> 3;   // 0..31 -> ij micro-rows
    const int tc     = tid & 7;    // 0..7  -> k  micro-cols

    // staging identity for this thread's ij column
    const int  ij   = ijbase + tid;
    const bool ijok = (ij < IJ);
    const int  ii   = ijok ? (ij / VJ) : 0;
    const int  jj   = ijok ? (ij - ii * VJ) : 0;
    const float* ap = audio + (size_t)b * T_ * A_ + (ii - 1);
    const float* vp = video + (size_t)b * T_ * V_ + (jj - 1);

    u64 acc[8][4];
#pragma unroll
    for (int i = 0; i < 8; i++)
#pragma unroll
        for (int j = 0; j < 4; j++) acc[i][j] = 0ull;

    for (int t0 = 0; t0 < T_; t0 += 32) {
        // stage av column for this thread's ij
#pragma unroll 4
        for (int tt = 0; tt < 32; tt++) {
            float w = 0.f;
            if (ijok) {
                const int t = t0 + tt;
                float a = (ii > 0) ? ap[t * A_] : 1.f;
                float v = (jj > 0) ? vp[t * V_] : 1.f;
                w = a * v;
            }
            av_s[tt][tid] = w;
        }
        // stage x1 tile (k==0 -> ones column; k>=XK -> zero pad)
        for (int idx = tid; idx < 32 * 64; idx += 256) {
            const int tt = idx >> 6;
            const int kk = idx & 63;
            const int k  = kbase + kk;
            float xv = 0.f;
            if (k == 0)       xv = 1.f;
            else if (k < XK)  xv = text[(size_t)(b * T_ + t0 + tt) * X_ + (k - 1)];
            xs[tt][kk] = xv;
        }
        __syncthreads();

#pragma unroll 4
        for (int tt = 0; tt < 32; tt++) {
            const float4 a0 = *(const float4*)&av_s[tt][tr * 8];
            const float4 a1 = *(const float4*)&av_s[tt][tr * 8 + 4];
            const u64* xp = (const u64*)&xs[tt][tc * 8];
            const u64 x0 = xp[0], x1 = xp[1], x2 = xp[2], x3 = xp[3];
            const float aa[8] = {a0.x, a0.y, a0.z, a0.w, a1.x, a1.y, a1.z, a1.w};
#pragma unroll
            for (int i = 0; i < 8; i++) {
                const u64 ad = pack2(aa[i], aa[i]);
                fma2(acc[i][0], ad, x0);
                fma2(acc[i][1], ad, x1);
                fma2(acc[i][2], ad, x2);
                fma2(acc[i][3], ad, x3);
            }
        }
        __syncthreads();
    }

    // store this thread's 8x8 micro-tile (k bounds-guarded)
#pragma unroll
    for (int i = 0; i < 8; i++) {
        const int oij = ijbase + tr * 8 + i;
        if (oij >= IJ) continue;
        float* dst = g_fusion + (size_t)b * FD + (size_t)oij * XK;
#pragma unroll
        for (int j = 0; j < 4; j++) {
            const int k = kbase + tc * 8 + j * 2;
            float lo, hi;
            unpack2(acc[i][j], lo, hi);
            if (k     < XK) dst[k]     = lo;
            if (k + 1 < XK) dst[k + 1] = hi;
        }
    }
}

// ---------------------------------------------------------------------------
// Stage 2: h1_pre partials. Split-K GEMM: [128 x FD] @ [FD x 128].
// 296 CTAs, each owns the full 128x128 output tile over its K-slice and
// writes a deterministic partial. 256 threads, 8x8 micro-tiles, FFMA2.
// ---------------------------------------------------------------------------
__global__ void __launch_bounds__(256)
gemm_kernel(const float* __restrict__ W1)
{
    __shared__ __align__(16) float As[KT][132];  // [kk][b], padded rows
    __shared__ __align__(16) float Bs[KT][128];  // [kk][p]

    const int tid = threadIdx.x;
    const int tr  = tid >> 4;   // 0..15 -> b rows tr*8..+7
    const int tc  = tid & 15;   // 0..15 -> p cols tc*8..+7

    u64 acc[8][4];
#pragma unroll
    for (int i = 0; i < 8; i++)
#pragma unroll
        for (int j = 0; j < 4; j++) acc[i][j] = 0ull;

    for (int tile = blockIdx.x; tile < NTILES; tile += NSPLIT) {
        const int kb = tile * KT;
        // load A-tile: As[kk][b] = fusion[b][kb+kk]  (coalesced over kk)
        {
            const int kk   = tid & 15;
            const int brow = tid >> 4;
            const int f    = kb + kk;
            const bool ok  = (f < FD);
#pragma unroll
            for (int u = 0; u < 8; u++) {
                const int b = u * 16 + brow;
                As[kk][b] = ok ? g_fusion[(size_t)b * FD + f] : 0.f;
            }
        }
        // load B-tile: Bs[kk][p] = W1[kb+kk][p]  (fully coalesced)
#pragma unroll
        for (int u = 0; u < 8; u++) {
            const int idx = u * 256 + tid;
            const int kk  = idx >> 7;
            const int p   = idx & 127;
            const int f   = kb + kk;
            Bs[kk][p] = (f < FD) ? W1[(size_t)f * PF + p] : 0.f;
        }
        __syncthreads();

#pragma unroll
        for (int kk = 0; kk < KT; kk++) {
            const float4 a0 = *(const float4*)&As[kk][tr * 8];
            const float4 a1 = *(const float4*)&As[kk][tr * 8 + 4];
            const u64* bp = (const u64*)&Bs[kk][tc * 8];
            const u64 b0 = bp[0], b1 = bp[1], b2 = bp[2], b3 = bp[3];
            const float aa[8] = {a0.x, a0.y, a0.z, a0.w, a1.x, a1.y, a1.z, a1.w};
#pragma unroll
            for (int i = 0; i < 8; i++) {
                const u64 ad = pack2(aa[i], aa[i]);
                fma2(acc[i][0], ad, b0);
                fma2(acc[i][1], ad, b1);
                fma2(acc[i][2], ad, b2);
                fma2(acc[i][3], ad, b3);
            }
        }
        __syncthreads();
    }

    // deterministic partial store
    float* base = g_part + (size_t)blockIdx.x * B_ * PF;
#pragma unroll
    for (int i = 0; i < 8; i++) {
        const int b = tr * 8 + i;
        u64* row = (u64*)(base + (size_t)b * PF + tc * 8);
#pragma unroll
        for (int j = 0; j < 4; j++) row[j] = acc[i][j];
    }
}

// ---------------------------------------------------------------------------
// Stage 3: reduce partials -> h1 (relu) -> h2 (relu) -> sigmoid*6-3.
// One CTA per batch row, 128 threads (one per hidden unit).
// ---------------------------------------------------------------------------
__global__ void __launch_bounds__(128)
mlp_kernel(const float* __restrict__ b1,
           const float* __restrict__ W2,
           const float* __restrict__ b2,
           const float* __restrict__ W3,
           const float* __restrict__ b3,
           float* __restrict__ out)
{
    __shared__ float h1[128];
    __shared__ float h2[128];
    __shared__ float red[128];
    const int b = blockIdx.x;
    const int p = threadIdx.x;

    float s = b1[p];
    const float* pp = g_part + (size_t)b * PF + p;
    for (int c = 0; c < NSPLIT; c++) s += pp[(size_t)c * B_ * PF];
    h1[p] = fmaxf(s, 0.f);
    __syncthreads();

    float s2 = b2[p];
#pragma unroll 4
    for (int q = 0; q < PF; q++) s2 = fmaf(h1[q], W2[q * PF + p], s2);
    h2[p] = fmaxf(s2, 0.f);
    __syncthreads();

    red[p] = h2[p] * W3[p];
    __syncthreads();
    for (int st = 64; st > 0; st >>= 1) {
        if (p < st) red[p] += red[p + st];
        __syncthreads();
    }
    if (p == 0) {
        const float z = red[0] + b3[0];
        out[b] = 6.f / (1.f + expf(-z)) - 3.f;
    }
}

// ---------------------------------------------------------------------------
extern "C" void kernel_launch(void* const* d_in, const int* in_sizes, int n_in,
                              void* d_out, int out_size)
{
    const float* audio = (const float*)d_in[0];
    const float* video = (const float*)d_in[1];
    const float* text  = (const float*)d_in[2];
    const float* W1    = (const float*)d_in[3];
    const float* b1    = (const float*)d_in[4];
    const float* W2    = (const float*)d_in[5];
    const float* b2    = (const float*)d_in[6];
    const float* W3    = (const float*)d_in[7];
    const float* b3    = (const float*)d_in[8];

    fusion_kernel<<<dim3((IJ + 255) / 256, 2, B_), 256>>>(audio, video, text);
    gemm_kernel<<<NSPLIT, 256>>>(W1);
    mlp_kernel<<<B_, 128>>>(b1, W2, b2, W3, b3, (float*)d_out);
}